// round 2
// baseline (speedup 1.0000x reference)
#include <cuda_runtime.h>
#include <math.h>

// Problem constants (fixed shapes for this problem instance)
#define MAXN 50000
#define D    128        // D_IN == D_OUT == 128
#define EPW  16         // edges per warp in SpMM

typedef unsigned long long u64;

// Scratch: support = (1-alpha)*hi + alpha*h0, [N, 128] fp32
__device__ float g_support[MAXN * D];

// ---------------------------------------------------------------------------
// Packed f32x2 helpers (Blackwell FFMA2 — only reachable via PTX)
// ---------------------------------------------------------------------------
__device__ __forceinline__ u64 pack2(float lo, float hi) {
    u64 r;
    asm("mov.b64 %0, {%1, %2};" : "=l"(r) : "f"(lo), "f"(hi));
    return r;
}
__device__ __forceinline__ void unpack2(u64 v, float& lo, float& hi) {
    asm("mov.b64 {%0, %1}, %2;" : "=f"(lo), "=f"(hi) : "l"(v));
}
__device__ __forceinline__ void fma2(u64& acc, u64 a, u64 b) {
    asm("fma.rn.f32x2 %0, %1, %2, %0;" : "+l"(acc) : "l"(a), "l"(b));
}

// ---------------------------------------------------------------------------
// Kernel 1: support = alpha * h0   (vectorized float4)
// ---------------------------------------------------------------------------
__global__ void init_support_kernel(const float* __restrict__ h0,
                                    const float* __restrict__ alpha_p,
                                    int n_vec4) {
    int i = blockIdx.x * blockDim.x + threadIdx.x;
    if (i >= n_vec4) return;
    float a = *alpha_p;
    float4 h = ((const float4*)h0)[i];
    float4 s;
    s.x = a * h.x; s.y = a * h.y; s.z = a * h.z; s.w = a * h.w;
    ((float4*)g_support)[i] = s;
}

// ---------------------------------------------------------------------------
// Kernel 2: SpMM scatter-add. Rows are sorted, so each warp walks a chunk of
// EPW edges, accumulating in registers (each lane owns 4 of 128 columns as a
// float4) and flushing with atomicAdd only when the row id changes.
// support[row] += (1-alpha) * val * x[col]
// ---------------------------------------------------------------------------
__device__ __forceinline__ void flush_row(int row, int lane, const float4& acc) {
    float* dst = &g_support[row * D + lane * 4];
    atomicAdd(dst + 0, acc.x);
    atomicAdd(dst + 1, acc.y);
    atomicAdd(dst + 2, acc.z);
    atomicAdd(dst + 3, acc.w);
}

__global__ void spmm_kernel(const float* __restrict__ x,
                            const int*   __restrict__ rows,
                            const int*   __restrict__ cols,
                            const float* __restrict__ vals,
                            const float* __restrict__ alpha_p,
                            int E) {
    int gwarp = (blockIdx.x * blockDim.x + threadIdx.x) >> 5;
    int lane  = threadIdx.x & 31;
    int e0 = gwarp * EPW;
    if (e0 >= E) return;
    int e1 = min(e0 + EPW, E);

    float oma = 1.0f - *alpha_p;
    const float4* x4 = (const float4*)x;

    float4 acc = make_float4(0.f, 0.f, 0.f, 0.f);
    int cur = rows[e0];

    for (int e = e0; e < e1; ++e) {
        int r = rows[e];          // uniform across warp -> broadcast load
        if (r != cur) {           // uniform branch
            flush_row(cur, lane, acc);
            acc = make_float4(0.f, 0.f, 0.f, 0.f);
            cur = r;
        }
        float v = oma * vals[e];
        float4 xv = x4[cols[e] * 32 + lane];   // gather one 512B row (L2 resident)
        acc.x += v * xv.x;
        acc.y += v * xv.y;
        acc.z += v * xv.z;
        acc.w += v * xv.w;
    }
    flush_row(cur, lane, acc);
}

// ---------------------------------------------------------------------------
// Kernel 3: out = theta * (support @ W) + (1-theta) * support + x
// Block: 256 threads, tile TM=64 rows x 128 cols.
// Thread (ty = warp 0..7, tx = lane 0..31) computes rows ty*8..ty*8+7,
// cols tx*4..tx*4+3. Accumulators held as packed f32x2 pairs; inner loop
// uses fma.rn.f32x2 (FFMA2: 2 FMAs/issue on the fma pipe).
// W staged through smem in 32-row K-chunks (16KB); support tile 32KB.
// ---------------------------------------------------------------------------
#define TM 64

__global__ __launch_bounds__(256) void gemm_epilogue_kernel(
        const float* __restrict__ W,
        const float* __restrict__ x,
        const float* __restrict__ lamda_p,
        const int*   __restrict__ layer_p,
        float* __restrict__ out,
        int N) {
    __shared__ float s_tile[TM * D];   // 32 KB
    __shared__ float s_W[32 * D];      // 16 KB  (total 48 KB static)

    float theta = logf(*lamda_p / (float)(*layer_p) + 1.0f);
    float omt   = 1.0f - theta;

    int tid = threadIdx.x;
    int tx  = tid & 31;
    int ty  = tid >> 5;
    int base = blockIdx.x * TM;

    // Load support tile [TM x 128] as float4 (2048 float4 / 256 thr = 8 each)
    {
        const float4* sup4 = (const float4*)g_support;
        float4* st4 = (float4*)s_tile;
        #pragma unroll
        for (int i = 0; i < 8; ++i) {
            int lin = i * 256 + tid;         // 0..2047
            int r = lin >> 5, c = lin & 31;
            float4 v = make_float4(0.f, 0.f, 0.f, 0.f);
            if (base + r < N) v = sup4[(base + r) * 32 + c];
            st4[lin] = v;
        }
    }

    // Packed accumulators: acc01[r] = cols (4tx+0, 4tx+1), acc23[r] = (4tx+2, 4tx+3)
    u64 acc01[8], acc23[8];
    #pragma unroll
    for (int r = 0; r < 8; ++r) { acc01[r] = 0ull; acc23[r] = 0ull; }

    const float4* W4 = (const float4*)W;
    float4* sW4 = (float4*)s_W;

    for (int kc = 0; kc < D; kc += 32) {
        __syncthreads();   // s_tile ready (kc=0) / previous s_W reads done
        #pragma unroll
        for (int i = 0; i < 4; ++i) {
            int lin = i * 256 + tid;         // 0..1023
            int r = lin >> 5, c = lin & 31;
            sW4[lin] = W4[(kc + r) * 32 + c];
        }
        __syncthreads();

        #pragma unroll 8
        for (int k = 0; k < 32; ++k) {
            float4 w = sW4[k * 32 + tx];     // conflict-free LDS.128
            u64 w01 = pack2(w.x, w.y);       // reg-pair alias (often free)
            u64 w23 = pack2(w.z, w.w);
            #pragma unroll
            for (int r = 0; r < 8; ++r) {
                float s = s_tile[(ty * 8 + r) * D + kc + k];  // warp broadcast
                u64 ss = pack2(s, s);        // alu-pipe mov, parallel to fma pipe
                fma2(acc01[r], ss, w01);
                fma2(acc23[r], ss, w23);
            }
        }
    }

    // Epilogue: theta*gemm + (1-theta)*support + x
    const float4* x4 = (const float4*)x;
    float4* out4 = (float4*)out;
    const float4* st4 = (const float4*)s_tile;
    #pragma unroll
    for (int r = 0; r < 8; ++r) {
        int m = base + ty * 8 + r;
        if (m < N) {
            float a0, a1, a2, a3;
            unpack2(acc01[r], a0, a1);
            unpack2(acc23[r], a2, a3);
            float4 sv = st4[(ty * 8 + r) * 32 + tx];
            float4 xv = x4[m * 32 + tx];
            float4 o;
            o.x = theta * a0 + omt * sv.x + xv.x;
            o.y = theta * a1 + omt * sv.y + xv.y;
            o.z = theta * a2 + omt * sv.z + xv.z;
            o.w = theta * a3 + omt * sv.w + xv.w;
            out4[m * 32 + tx] = o;
        }
    }
}

// ---------------------------------------------------------------------------
// Launch
// Inputs (metadata order):
//  0: x        float [N*128]
//  1: h0       float [N*128]
//  2: weight   float [128*128]
//  3: lamda    float [1]
//  4: alpha    float [1]
//  5: adj_rows int   [E]
//  6: adj_cols int   [E]
//  7: adj_vals float [E]
//  8: layer_idx int  [1]
// Output: float [N*128]
// ---------------------------------------------------------------------------
extern "C" void kernel_launch(void* const* d_in, const int* in_sizes, int n_in,
                              void* d_out, int out_size) {
    const float* x      = (const float*)d_in[0];
    const float* h0     = (const float*)d_in[1];
    const float* weight = (const float*)d_in[2];
    const float* lamda  = (const float*)d_in[3];
    const float* alpha  = (const float*)d_in[4];
    const int*   rows   = (const int*)d_in[5];
    const int*   cols   = (const int*)d_in[6];
    const float* vals   = (const float*)d_in[7];
    const int*   layer  = (const int*)d_in[8];
    float* out = (float*)d_out;

    int N = in_sizes[0] / D;
    int E = in_sizes[5];

    // 1) support = alpha * h0
    int n_vec4 = N * (D / 4);
    init_support_kernel<<<(n_vec4 + 255) / 256, 256>>>(h0, alpha, n_vec4);

    // 2) SpMM scatter-add (warp per EPW-edge chunk)
    int n_warps  = (E + EPW - 1) / EPW;
    int n_blocks = (n_warps * 32 + 255) / 256;
    spmm_kernel<<<n_blocks, 256>>>(x, rows, cols, vals, alpha, E);

    // 3) GEMM + epilogue
    int g_blocks = (N + TM - 1) / TM;
    gemm_epilogue_kernel<<<g_blocks, 256>>>(weight, x, lamda, layer, out, N);
}

// round 6
// speedup vs baseline: 1.1116x; 1.1116x over previous
#include <cuda_runtime.h>
#include <math.h>

#define D  128        // D_IN == D_OUT
#define TM 64         // rows per block

typedef unsigned long long u64;

// ---------------------------------------------------------------------------
// Packed f32x2 helpers (Blackwell FFMA2 — only reachable via PTX)
// ---------------------------------------------------------------------------
__device__ __forceinline__ u64 pack2(float lo, float hi) {
    u64 r;
    asm("mov.b64 %0, {%1, %2};" : "=l"(r) : "f"(lo), "f"(hi));
    return r;
}
__device__ __forceinline__ void unpack2(u64 v, float& lo, float& hi) {
    asm("mov.b64 {%0, %1}, %2;" : "=f"(lo), "=f"(hi) : "l"(v));
}
__device__ __forceinline__ void fma2(u64& acc, u64 a, u64 b) {
    asm("fma.rn.f32x2 %0, %1, %2, %0;" : "+l"(acc) : "l"(a), "l"(b));
}

__device__ __forceinline__ int lower_bound(const int* __restrict__ a, int n, int key) {
    int lo = 0, hi = n;
    while (lo < hi) {
        int mid = (lo + hi) >> 1;
        if (a[mid] < key) lo = mid + 1; else hi = mid;
    }
    return lo;
}

// ---------------------------------------------------------------------------
// Fused kernel, one block per TM=64 output rows:
//   Phase 1a: smem tile = alpha * h0.
//   Phase 1b: warp w owns rows base+w*8..+7. Binary-search its edge segment,
//     accumulate (1-a)*val*x[col] in a register float4 (4-cyc FFMA chain),
//     flushing to the smem tile only on row change (uniform branch; ~1 RMW
//     per row instead of per edge — smem has no store-forwarding). Gathers
//     are branch-independent -> unroll 8 exposes MLP~8 to hide L2 latency.
//   Phase 2: out = theta*(tile @ W) + (1-theta)*tile + x via packed
//     fma.rn.f32x2; W staged through smem in 32-row K-chunks.
// ---------------------------------------------------------------------------
__global__ __launch_bounds__(256) void fused_gcn_kernel(
        const float* __restrict__ x,
        const float* __restrict__ h0,
        const float* __restrict__ W,
        const float* __restrict__ lamda_p,
        const float* __restrict__ alpha_p,
        const int*   __restrict__ rows,
        const int*   __restrict__ cols,
        const float* __restrict__ vals,
        const int*   __restrict__ layer_p,
        float* __restrict__ out,
        int N, int E) {
    __shared__ float s_tile[TM * D];   // 32 KB  support tile
    __shared__ float s_W[32 * D];      // 16 KB  W K-chunk   (48 KB total)

    int tid  = threadIdx.x;
    int tx   = tid & 31;
    int ty   = tid >> 5;
    int base = blockIdx.x * TM;

    float alpha = *alpha_p;
    float oma   = 1.0f - alpha;

    const float4* x4  = (const float4*)x;
    const float4* h04 = (const float4*)h0;
    float4* st4 = (float4*)s_tile;

    // ---- Phase 1a: tile = alpha * h0 (zeros for OOB rows)
    #pragma unroll
    for (int rr = 0; rr < 8; ++rr) {
        int r = base + ty * 8 + rr;
        float4 v = make_float4(0.f, 0.f, 0.f, 0.f);
        if (r < N) {
            float4 h = h04[r * 32 + tx];
            v.x = alpha * h.x; v.y = alpha * h.y;
            v.z = alpha * h.z; v.w = alpha * h.w;
        }
        st4[(ty * 8 + rr) * 32 + tx] = v;
    }

    // ---- Phase 1b: edge gather, register-accumulate, flush on row change
    {
        int r0   = base + ty * 8;
        int rhi  = min(r0 + 8, N);
        int e    = (r0 < N) ? lower_bound(rows, E, r0)  : E;
        int eend = (r0 < N) ? lower_bound(rows, E, rhi) : E;

        if (e < eend) {
            float4 acc = make_float4(0.f, 0.f, 0.f, 0.f);
            int cur = rows[e];                 // uniform across warp

            #pragma unroll 8
            for (; e < eend; ++e) {
                int r = rows[e];               // uniform broadcast load
                if (r != cur) {                // uniform branch, ~once per row
                    float4* p = &st4[(cur - base) * 32 + tx];
                    float4 t = *p;
                    t.x += acc.x; t.y += acc.y; t.z += acc.z; t.w += acc.w;
                    *p = t;
                    acc = make_float4(0.f, 0.f, 0.f, 0.f);
                    cur = r;
                }
                float  v  = oma * vals[e];
                float4 xv = x4[cols[e] * 32 + tx];   // 512B L2 gather, pipelined
                acc.x += v * xv.x;
                acc.y += v * xv.y;
                acc.z += v * xv.z;
                acc.w += v * xv.w;
            }
            float4* p = &st4[(cur - base) * 32 + tx];
            float4 t = *p;
            t.x += acc.x; t.y += acc.y; t.z += acc.z; t.w += acc.w;
            *p = t;
        }
    }

    // ---- Phase 2: GEMM + epilogue
    float theta = logf(*lamda_p / (float)(*layer_p) + 1.0f);
    float omt   = 1.0f - theta;

    u64 acc01[8], acc23[8];
    #pragma unroll
    for (int r = 0; r < 8; ++r) { acc01[r] = 0ull; acc23[r] = 0ull; }

    const float4* W4  = (const float4*)W;
    float4* sW4 = (float4*)s_W;

    for (int kc = 0; kc < D; kc += 32) {
        __syncthreads();   // s_W reuse barrier (and tile visibility, 1st iter)
        #pragma unroll
        for (int i = 0; i < 4; ++i) {
            int lin = i * 256 + tid;         // 0..1023
            int r = lin >> 5, c = lin & 31;
            sW4[lin] = W4[(kc + r) * 32 + c];
        }
        __syncthreads();

        #pragma unroll 8
        for (int k = 0; k < 32; ++k) {
            float4 w = sW4[k * 32 + tx];     // conflict-free LDS.128
            u64 w01 = pack2(w.x, w.y);
            u64 w23 = pack2(w.z, w.w);
            #pragma unroll
            for (int r = 0; r < 8; ++r) {
                float s = s_tile[(ty * 8 + r) * D + kc + k];  // warp broadcast
                u64 ss = pack2(s, s);        // alu pipe, parallel to fma pipe
                fma2(acc01[r], ss, w01);
                fma2(acc23[r], ss, w23);
            }
        }
    }

    // Epilogue: theta*gemm + (1-theta)*support + x
    float4* out4 = (float4*)out;
    #pragma unroll
    for (int r = 0; r < 8; ++r) {
        int m = base + ty * 8 + r;
        if (m < N) {
            float a0, a1, a2, a3;
            unpack2(acc01[r], a0, a1);
            unpack2(acc23[r], a2, a3);
            float4 sv = st4[(ty * 8 + r) * 32 + tx];
            float4 xv = x4[m * 32 + tx];
            float4 o;
            o.x = theta * a0 + omt * sv.x + xv.x;
            o.y = theta * a1 + omt * sv.y + xv.y;
            o.z = theta * a2 + omt * sv.z + xv.z;
            o.w = theta * a3 + omt * sv.w + xv.w;
            out4[m * 32 + tx] = o;
        }
    }
}

// ---------------------------------------------------------------------------
// Launch.  Inputs (metadata order):
//  0: x float[N*128]  1: h0 float[N*128]  2: weight float[128*128]
//  3: lamda float[1]  4: alpha float[1]
//  5: adj_rows int[E] 6: adj_cols int[E] 7: adj_vals float[E]
//  8: layer_idx int[1]          Output: float[N*128]
// ---------------------------------------------------------------------------
extern "C" void kernel_launch(void* const* d_in, const int* in_sizes, int n_in,
                              void* d_out, int out_size) {
    const float* x      = (const float*)d_in[0];
    const float* h0     = (const float*)d_in[1];
    const float* weight = (const float*)d_in[2];
    const float* lamda  = (const float*)d_in[3];
    const float* alpha  = (const float*)d_in[4];
    const int*   rows   = (const int*)d_in[5];
    const int*   cols   = (const int*)d_in[6];
    const float* vals   = (const float*)d_in[7];
    const int*   layer  = (const int*)d_in[8];
    float* out = (float*)d_out;

    int N = in_sizes[0] / D;
    int E = in_sizes[5];

    int blocks = (N + TM - 1) / TM;
    fused_gcn_kernel<<<blocks, 256>>>(x, h0, weight, lamda, alpha,
                                      rows, cols, vals, layer, out, N, E);
}